// round 4
// baseline (speedup 1.0000x reference)
#include <cuda_runtime.h>
#include <math.h>

#define BB 8
#define TT 1024
#define DD 128
#define UU 2048
#define OUTF (DD + UU)
#define NCTA 128
#define COLS 16
#define NTHR 512
#define NWARP (NTHR / 32)

// SMEM layout (floats). First 4 floats = two 8-byte mbarriers.
#define MB_FLOATS  4
#define W_FLOATS   (UU * COLS)    // 32768  w_res slice [2048][16]
#define S_FLOATS   (UU * BB)      // 16384  state        [2048][8]
#define WI_FLOATS  (DD * COLS)    // 2048   w_in slice   [128][16]
#define BI_FLOATS  16
#define RED_PAIRS  (64 * NWARP)   // [16 warps][64 og] f32x2 partials
#define SMEM_FLOATS (MB_FLOATS + W_FLOATS + S_FLOATS + WI_FLOATS + BI_FLOATS + RED_PAIRS * 2)
#define SMEM_BYTES  (SMEM_FLOATS * 4)   // ~213 KB < 227 KB

#define CHUNK_BYTES (S_FLOATS / 2 * 4)  // 32768 B per state chunk

__device__ float g_state[2][UU * BB];     // ping-pong state, layout [k][b]
__device__ unsigned g_bar_count;          // zero-init
__device__ unsigned g_bar_gen;            // monotone across replays (read-before-arrive)

// ---- TMA bulk copy + mbarrier (replaces 4096 LDGSTS/step with 2 UBLKCP) ----
__device__ __forceinline__ void mbar_init(unsigned mbar, unsigned count) {
    asm volatile("mbarrier.init.shared.b64 [%0], %1;" :: "r"(mbar), "r"(count) : "memory");
}
__device__ __forceinline__ void mbar_expect_tx(unsigned mbar, unsigned bytes) {
    asm volatile("mbarrier.arrive.expect_tx.shared.b64 _, [%0], %1;"
                 :: "r"(mbar), "r"(bytes) : "memory");
}
__device__ __forceinline__ void bulk_cp(unsigned dst, const void* src, unsigned bytes,
                                        unsigned mbar) {
    asm volatile(
        "cp.async.bulk.shared::cluster.global.mbarrier::complete_tx::bytes "
        "[%0], [%1], %2, [%3];"
        :: "r"(dst), "l"(src), "r"(bytes), "r"(mbar) : "memory");
}
__device__ __forceinline__ void mbar_wait(unsigned mbar, unsigned parity) {
    unsigned done;
    asm volatile(
        "{\n\t.reg .pred p;\n\t"
        "mbarrier.try_wait.parity.acquire.cta.shared::cta.b64 p, [%1], %2;\n\t"
        "selp.b32 %0, 1, 0, p;\n\t}"
        : "=r"(done) : "r"(mbar), "r"(parity) : "memory");
    if (!done) {
        asm volatile(
            "{\n\t.reg .pred P1;\n\t"
            "W_%=:\n\t"
            "mbarrier.try_wait.parity.acquire.cta.shared::cta.b64 P1, [%0], %1, 0x989680;\n\t"
            "@P1 bra.uni D_%=;\n\t"
            "bra.uni W_%=;\n\t"
            "D_%=:\n\t}"
            :: "r"(mbar), "r"(parity) : "memory");
    }
}

// packed fp32x2 FMA — ptxas never emits this from C++; doubles fp32 MAC rate
__device__ __forceinline__ void ffma2(unsigned long long& acc, unsigned long long a,
                                      unsigned long long b) {
    asm("fma.rn.f32x2 %0, %1, %2, %0;" : "+l"(acc) : "l"(a), "l"(b));
}
__device__ __forceinline__ unsigned long long dup2(float x) {
    unsigned long long r;
    unsigned xi = __float_as_uint(x);
    asm("mov.b64 %0, {%1, %1};" : "=l"(r) : "r"(xi));
    return r;
}
__device__ __forceinline__ unsigned long long padd2(unsigned long long a,
                                                    unsigned long long b) {
    unsigned long long r;
    asm("add.rn.f32x2 %0, %1, %2;" : "=l"(r) : "l"(a), "l"(b));
    return r;
}
__device__ __forceinline__ unsigned long long bfly2(unsigned long long v, int m) {
    unsigned lo = (unsigned)v, hi = (unsigned)(v >> 32);
    lo = __shfl_xor_sync(0xffffffffu, lo, m);
    hi = __shfl_xor_sync(0xffffffffu, hi, m);
    unsigned long long r;
    asm("mov.b64 %0, {%1, %2};" : "=l"(r) : "r"(lo), "r"(hi));
    return r;
}

// Grid-wide barrier: all 128 CTAs co-resident (1 CTA/SM via SMEM footprint).
__device__ __forceinline__ void grid_barrier() {
    __syncthreads();
    if (threadIdx.x == 0) {
        __threadfence();
        unsigned gen;
        asm volatile("ld.acquire.gpu.u32 %0, [%1];" : "=r"(gen) : "l"(&g_bar_gen));
        if (atomicAdd(&g_bar_count, 1) == NCTA - 1) {
            g_bar_count = 0;
            asm volatile("st.release.gpu.u32 [%0], %1;" :: "l"(&g_bar_gen), "r"(gen + 1)
                         : "memory");
        } else {
            unsigned cur;
            do {
                asm volatile("ld.acquire.gpu.u32 %0, [%1];" : "=r"(cur) : "l"(&g_bar_gen));
                if (cur != gen) break;
                __nanosleep(20);
            } while (true);
        }
    }
    __syncthreads();
}

// 16 k-iterations (k = kb + ks + 64*i), 8 FFMA2 each.
__device__ __forceinline__ void dot_block(const float* __restrict__ s_sh,
                                          const float* __restrict__ w_sh, int kb,
                                          int ks, int b0, int j0,
                                          unsigned long long acc[2][4]) {
#pragma unroll
    for (int i = 0; i < 16; ++i) {
        int k = kb + ks + i * 64;  // interleaved slices: conflict-free SMEM rows
        float2 s01 = *(const float2*)(s_sh + k * 8 + b0);
        ulonglong2 wA = *(const ulonglong2*)(w_sh + k * 16 + j0);
        ulonglong2 wB = *(const ulonglong2*)(w_sh + k * 16 + j0 + 4);
        unsigned long long d0 = dup2(s01.x);
        unsigned long long d1 = dup2(s01.y);
        ffma2(acc[0][0], wA.x, d0); ffma2(acc[0][1], wA.y, d0);
        ffma2(acc[0][2], wB.x, d0); ffma2(acc[0][3], wB.y, d0);
        ffma2(acc[1][0], wA.x, d1); ffma2(acc[1][1], wA.y, d1);
        ffma2(acc[1][2], wB.x, d1); ffma2(acc[1][3], wB.y, d1);
    }
}

__global__ void __launch_bounds__(NTHR, 1)
esn_kernel(const float* __restrict__ inputs, const float* __restrict__ w_in_g,
           const float* __restrict__ b_in_g, const float* __restrict__ w_res_g,
           float* __restrict__ out) {
    extern __shared__ float smem[];
    float* w_sh  = smem + MB_FLOATS;        // [2048][16]
    float* s_sh  = w_sh + W_FLOATS;         // [2048][8]
    float* wi_sh = s_sh + S_FLOATS;         // [128][16]
    float* bi_sh = wi_sh + WI_FLOATS;       // [16]
    unsigned long long* red = (unsigned long long*)(bi_sh + BI_FLOATS);  // [16w][64og]

    const int tid = threadIdx.x;
    const int cta = blockIdx.x;
    const int col0 = cta * COLS;

    const unsigned mb0 = (unsigned)__cvta_generic_to_shared(smem);
    const unsigned mb1 = mb0 + 8;
    const unsigned s_base = (unsigned)__cvta_generic_to_shared(s_sh);

    if (tid == 0) {
        mbar_init(mb0, 1);
        mbar_init(mb1, 1);
        asm volatile("fence.proxy.async.shared::cta;" ::: "memory");
    }

    // Stage w_res slice [2048 x 16] once
    for (int r = tid; r < UU; r += NTHR) {
        const float4* src = (const float4*)(w_res_g + (size_t)r * UU + col0);
        float4* dst = (float4*)(w_sh + r * COLS);
        dst[0] = src[0]; dst[1] = src[1]; dst[2] = src[2]; dst[3] = src[3];
    }
    for (int r = tid; r < DD; r += NTHR) {
        const float4* src = (const float4*)(w_in_g + (size_t)r * UU + col0);
        float4* dst = (float4*)(wi_sh + r * COLS);
        dst[0] = src[0]; dst[1] = src[1]; dst[2] = src[2]; dst[3] = src[3];
    }
    if (tid < COLS) bi_sh[tid] = b_in_g[col0 + tid];

    // Zero initial state (buffer 0); buffer 1 fully overwritten at t=0.
    for (int i = cta * NTHR + tid; i < UU * BB; i += NCTA * NTHR) g_state[0][i] = 0.0f;

    grid_barrier();

    // Decomposition: 64 k-slices x (4 b-pairs x 2 j-groups)
    const int ks = tid >> 3;            // 0..63
    const int o = tid & 7;
    const int b0 = (o >> 1) << 1;       // 0,2,4,6
    const int j0 = (o & 1) << 3;        // 0 or 8
    const int warp = tid >> 5;
    const int lane = tid & 31;

    int cur = 0;
    for (int t = 0; t < TT; ++t) {
        const float* sg = g_state[cur];
        const unsigned parity = t & 1;

        // Two bulk TMA copies replace 4096 LDGSTS: issue cost ~2 instr from 1 thread.
        if (tid == 0) {
            mbar_expect_tx(mb0, CHUNK_BYTES);
            bulk_cp(s_base, sg, CHUNK_BYTES, mb0);
            mbar_expect_tx(mb1, CHUNK_BYTES);
            bulk_cp(s_base + CHUNK_BYTES, sg + S_FLOATS / 2, CHUNK_BYTES, mb1);
        }

        // x_t for this thread's (b0,b0+1) x (ks, ks+64): L2-resident, hidden by dot
        const float* xb0 = inputs + ((size_t)(b0 * TT + t)) * DD;
        const float* xb1 = inputs + ((size_t)((b0 + 1) * TT + t)) * DD;
        float x00 = __ldg(xb0 + ks);
        float x01 = __ldg(xb0 + ks + 64);
        float x10 = __ldg(xb1 + ks);
        float x11 = __ldg(xb1 + ks + 64);

        unsigned long long acc[2][4];
#pragma unroll
        for (int a1 = 0; a1 < 2; ++a1)
#pragma unroll
            for (int a2 = 0; a2 < 4; ++a2) acc[a1][a2] = 0ULL;

        mbar_wait(mb0, parity);
        dot_block(s_sh, w_sh, 0, ks, b0, j0, acc);       // chunk0 (chunk1 in flight)
        mbar_wait(mb1, parity);
        dot_block(s_sh, w_sh, 1024, ks, b0, j0, acc);    // chunk1

        // folded input projection x_t @ Win (K = 128), x from registers
#pragma unroll
        for (int i = 0; i < 2; ++i) {
            int k = ks + i * 64;
            unsigned long long d0 = dup2(i == 0 ? x00 : x01);
            unsigned long long d1 = dup2(i == 0 ? x10 : x11);
            ulonglong2 wA = *(const ulonglong2*)(wi_sh + k * 16 + j0);
            ulonglong2 wB = *(const ulonglong2*)(wi_sh + k * 16 + j0 + 4);
            ffma2(acc[0][0], wA.x, d0); ffma2(acc[0][1], wA.y, d0);
            ffma2(acc[0][2], wB.x, d0); ffma2(acc[0][3], wB.y, d0);
            ffma2(acc[1][0], wA.x, d1); ffma2(acc[1][1], wA.y, d1);
            ffma2(acc[1][2], wB.x, d1); ffma2(acc[1][3], wB.y, d1);
        }

        // In-register reduce over the warp's 4 k-slices (lane bits 3,4)
#pragma unroll
        for (int bi = 0; bi < 2; ++bi)
#pragma unroll
            for (int pi = 0; pi < 4; ++pi) {
                unsigned long long v = acc[bi][pi];
                v = padd2(v, bfly2(v, 8));
                v = padd2(v, bfly2(v, 16));
                acc[bi][pi] = v;
            }
        if (lane < 8) {
#pragma unroll
            for (int bi = 0; bi < 2; ++bi)
#pragma unroll
                for (int pi = 0; pi < 4; ++pi) {
                    int og = (b0 + bi) * 8 + ((j0 >> 1) + pi);
                    red[warp * 64 + og] = acc[bi][pi];
                }
        }
        __syncthreads();

        // Final reduce over 16 warps + epilogue
        if (tid < 64) {
            unsigned long long v = red[tid];
#pragma unroll
            for (int w = 1; w < NWARP; ++w) v = padd2(v, red[w * 64 + tid]);
            float v0 = __uint_as_float((unsigned)v);
            float v1 = __uint_as_float((unsigned)(v >> 32));
            int b = tid >> 3, p = tid & 7;
            int c0 = col0 + 2 * p;
            float pre0 = v0 + bi_sh[2 * p];
            float pre1 = v1 + bi_sh[2 * p + 1];
            float so0 = s_sh[c0 * 8 + b];
            float so1 = s_sh[(c0 + 1) * 8 + b];
            float n0 = 0.5f * so0 + 0.5f * tanhf(pre0);
            float n1 = 0.5f * so1 + 0.5f * tanhf(pre1);
            float* sn = g_state[cur ^ 1];
            __stcg(sn + c0 * 8 + b, n0);           // L2-resident, no L1 staleness
            __stcg(sn + (c0 + 1) * 8 + b, n1);
            float2 ov;                             // PowerIndex: even col squared
            ov.x = n0 * n0;
            ov.y = n1;
            *(float2*)(out + ((size_t)(b * TT + t)) * OUTF + DD + c0) = ov;
        }

        grid_barrier();
        cur ^= 1;
    }
}

__global__ void copy_inputs_kernel(const float4* __restrict__ in, float* __restrict__ out) {
    int idx = blockIdx.x * blockDim.x + threadIdx.x;
    if (idx < BB * TT * DD / 4) {
        int bt = idx >> 5;  // 32 float4 per (b,t) row
        int q = idx & 31;
        float4 v = in[idx];
        *(float4*)(out + (size_t)bt * OUTF + q * 4) = v;
    }
}

extern "C" void kernel_launch(void* const* d_in, const int* in_sizes, int n_in,
                              void* d_out, int out_size) {
    const float* inputs = (const float*)d_in[0];
    const float* w_in   = (const float*)d_in[1];
    const float* b_in   = (const float*)d_in[2];
    const float* w_res  = (const float*)d_in[3];
    float* out = (float*)d_out;

    cudaFuncSetAttribute(esn_kernel, cudaFuncAttributeMaxDynamicSharedMemorySize, SMEM_BYTES);

    copy_inputs_kernel<<<(BB * TT * DD / 4 + 255) / 256, 256>>>((const float4*)inputs, out);
    esn_kernel<<<NCTA, NTHR, SMEM_BYTES>>>(inputs, w_in, b_in, w_res, out);
}

// round 5
// speedup vs baseline: 1.2573x; 1.2573x over previous
#include <cuda_runtime.h>
#include <math.h>

#define BB 8
#define TT 1024
#define DD 128
#define UU 2048
#define OUTF (DD + UU)
#define NCTA 128
#define COLS 16
#define NTHR 512
#define NWARP 16

typedef unsigned long long ull;

// SMEM layout (floats)
#define W_FLOATS   (UU * COLS)    // 32768  w_res slice [2048][16], 64B rows, chunk-swizzled
#define S_FLOATS   (UU * BB)      // 16384  state [2048][8], 32B rows, half-swizzled
#define WI_FLOATS  (DD * COLS)    // 2048   w_in slice, same swizzle as w
#define BI_FLOATS  16
#define RED_ULL    (NWARP * 32)   // [16 warps][32 lanes] f32x2 warp partials
#define SMEM_FLOATS (W_FLOATS + S_FLOATS + WI_FLOATS + BI_FLOATS + RED_ULL * 2)
#define SMEM_BYTES  (SMEM_FLOATS * 4)   // ~209 KB < 227 KB

__device__ float g_state[2][UU * BB];   // ping-pong state, linear [k][b]
__device__ unsigned g_bar_count;        // init-barrier (once per launch)
__device__ unsigned g_bar_gen;          // monotone across replays
__device__ unsigned g_step_count;       // per-step arrivals, reset each launch

__device__ __forceinline__ void cp16(unsigned dst, const void* src) {
    asm volatile("cp.async.cg.shared.global [%0], [%1], 16;" :: "r"(dst), "l"(src));
}
__device__ __forceinline__ void cp_commit() { asm volatile("cp.async.commit_group;"); }
template <int N>
__device__ __forceinline__ void cp_wait() {
    asm volatile("cp.async.wait_group %0;" :: "n"(N));
}
// packed fp32x2 ops — ptxas never emits these from C++
__device__ __forceinline__ void ffma2(ull& acc, ull a, ull b) {
    asm("fma.rn.f32x2 %0, %1, %2, %0;" : "+l"(acc) : "l"(a), "l"(b));
}
__device__ __forceinline__ ull dup2(float x) {
    ull r;
    unsigned xi = __float_as_uint(x);
    asm("mov.b64 %0, {%1, %1};" : "=l"(r) : "r"(xi));
    return r;
}
__device__ __forceinline__ ull padd2(ull a, ull b) {
    ull r;
    asm("add.rn.f32x2 %0, %1, %2;" : "=l"(r) : "l"(a), "l"(b));
    return r;
}
__device__ __forceinline__ ull bfly2(ull v, int m) {
    unsigned lo = (unsigned)v, hi = (unsigned)(v >> 32);
    lo = __shfl_xor_sync(0xffffffffu, lo, m);
    hi = __shfl_xor_sync(0xffffffffu, hi, m);
    ull r;
    asm("mov.b64 %0, {%1, %2};" : "=l"(r) : "r"(lo), "r"(hi));
    return r;
}

// init-only grid barrier (proven pattern from earlier rounds)
__device__ __forceinline__ void grid_barrier_init() {
    __syncthreads();
    if (threadIdx.x == 0) {
        __threadfence();
        unsigned gen;
        asm volatile("ld.acquire.gpu.u32 %0, [%1];" : "=r"(gen) : "l"(&g_bar_gen));
        if (atomicAdd(&g_bar_count, 1) == NCTA - 1) {
            g_bar_count = 0;
            asm volatile("st.release.gpu.u32 [%0], %1;" :: "l"(&g_bar_gen), "r"(gen + 1)
                         : "memory");
        } else {
            unsigned cur;
            do {
                asm volatile("ld.acquire.gpu.u32 %0, [%1];" : "=r"(cur) : "l"(&g_bar_gen));
                if (cur != gen) break;
                __nanosleep(32);
            } while (true);
        }
    }
    __syncthreads();
}

// One k-row: 32B state (8 b) + 32B weights (8 cols) -> 64 MACs (32 FFMA2).
// acc[b][cp]: cp = column pair (2 cols packed in f32x2).
__device__ __forceinline__ void dot_row(const float* __restrict__ s_sh,
                                        const float* __restrict__ w_sh, int k,
                                        int b2, int p0f, int p1f, ull acc[8][4]) {
    float4 sA = *(const float4*)(s_sh + k * 8 + (b2 << 2));          // b0..3
    float4 sB = *(const float4*)(s_sh + k * 8 + ((1 ^ b2) << 2));    // b4..7
    ulonglong2 w0 = *(const ulonglong2*)(w_sh + k * 16 + p0f);       // cols j0..j0+3
    ulonglong2 w1 = *(const ulonglong2*)(w_sh + k * 16 + p1f);       // cols j0+4..j0+7
#define DO_B(bf, val)                                   \
    {                                                   \
        ull d = dup2(val);                              \
        ffma2(acc[bf][0], w0.x, d);                     \
        ffma2(acc[bf][1], w0.y, d);                     \
        ffma2(acc[bf][2], w1.x, d);                     \
        ffma2(acc[bf][3], w1.y, d);                     \
    }
    DO_B(0, sA.x) DO_B(1, sA.y) DO_B(2, sA.z) DO_B(3, sA.w)
    DO_B(4, sB.x) DO_B(5, sB.y) DO_B(6, sB.z) DO_B(7, sB.w)
#undef DO_B
}

__global__ void __launch_bounds__(NTHR, 1)
esn_kernel(const float* __restrict__ inputs, const float* __restrict__ w_in_g,
           const float* __restrict__ b_in_g, const float* __restrict__ w_res_g,
           float* __restrict__ out) {
    extern __shared__ float smem[];
    float* w_sh  = smem;                    // [2048][16]
    float* s_sh  = w_sh + W_FLOATS;         // [2048][8]
    float* wi_sh = s_sh + S_FLOATS;         // [128][16]
    float* bi_sh = wi_sh + WI_FLOATS;       // [16]
    ull* red = (ull*)(bi_sh + BI_FLOATS);   // [16 warps][32 lanes]

    const int tid = threadIdx.x;
    const int cta = blockIdx.x;
    const int col0 = cta * COLS;

    if (cta == 0 && tid == 0) g_step_count = 0;   // fresh epoch per launch/replay

    // Stage w_res slice with chunk swizzle: row r (64B = 4 x 16B chunks),
    // logical chunk c stored at position c ^ ((r>>1)&3)  -> conflict-free LDS.128.
    for (int r = tid; r < UU; r += NTHR) {
        const float4* src = (const float4*)(w_res_g + (size_t)r * UU + col0);
        int m = (r >> 1) & 3;
        float4* dst = (float4*)(w_sh + r * COLS);
        dst[0 ^ m] = src[0]; dst[1 ^ m] = src[1];
        dst[2 ^ m] = src[2]; dst[3 ^ m] = src[3];
    }
    for (int r = tid; r < DD; r += NTHR) {
        const float4* src = (const float4*)(w_in_g + (size_t)r * UU + col0);
        int m = (r >> 1) & 3;
        float4* dst = (float4*)(wi_sh + r * COLS);
        dst[0 ^ m] = src[0]; dst[1 ^ m] = src[1];
        dst[2 ^ m] = src[2]; dst[3 ^ m] = src[3];
    }
    if (tid < COLS) bi_sh[tid] = b_in_g[col0 + tid];

    // Zero initial state (buffer 0)
    for (int i = cta * NTHR + tid; i < UU * BB; i += NCTA * NTHR) g_state[0][i] = 0.0f;

    grid_barrier_init();

    // Decomposition: 256 k-slices x 2 column-halves.
    const int ks = tid & 255;           // k-slice
    const int jh = tid >> 8;            // 0: cols 0-7, 1: cols 8-15
    const int warp = tid >> 5;
    const int lane = tid & 31;
    const int b2 = (ks >> 2) & 1;       // state half swizzle key (constant per thread)
    const int m = (ks >> 1) & 3;        // weight chunk swizzle key
    const int p0f = ((2 * jh) ^ m) << 2;
    const int p1f = ((2 * jh + 1) ^ m) << 2;
    const unsigned s_base = (unsigned)__cvta_generic_to_shared(s_sh);

    for (int t = 0; t < TT; ++t) {
        // x_t values for this thread's d=ks (independent of state; in flight during poll)
        float xv[8];
        if (ks < DD) {
            const float* xp = inputs + (size_t)t * DD + ks;
#pragma unroll
            for (int b = 0; b < 8; ++b) xv[b] = __ldg(xp + (size_t)b * TT * DD);
        }

        // Step gate: wait until all 128 CTAs arrived for step t-1.
        if (tid == 0) {
            const unsigned target = (unsigned)(128u * (unsigned)t);
            unsigned v;
            do {
                asm volatile("ld.acquire.gpu.global.u32 %0, [%1];"
                             : "=r"(v) : "l"(&g_step_count));
            } while (v < target);
        }
        __syncthreads();

        // Broadcast state: 4 chunks x 16KB, swizzled dst (16B granule):
        // granule g stored at g ^ ((g>>3)&1)  (swaps 16B halves of 32B rows).
        const float* sg = g_state[t & 1];
#pragma unroll
        for (int c = 0; c < 4; ++c) {
            int g0 = c * 1024 + tid;
            cp16(s_base + ((unsigned)(g0 ^ ((g0 >> 3) & 1)) << 4), sg + g0 * 4);
            int g1 = g0 + 512;
            cp16(s_base + ((unsigned)(g1 ^ ((g1 >> 3) & 1)) << 4), sg + g1 * 4);
            cp_commit();
        }

        ull acc[8][4];
#pragma unroll
        for (int b = 0; b < 8; ++b)
#pragma unroll
            for (int c = 0; c < 4; ++c) acc[b][c] = 0ULL;

        // Input projection (overlaps chunk-0 flight)
        if (ks < DD) {
            ulonglong2 w0 = *(const ulonglong2*)(wi_sh + ks * 16 + p0f);
            ulonglong2 w1 = *(const ulonglong2*)(wi_sh + ks * 16 + p1f);
#pragma unroll
            for (int b = 0; b < 8; ++b) {
                ull d = dup2(xv[b]);
                ffma2(acc[b][0], w0.x, d); ffma2(acc[b][1], w0.y, d);
                ffma2(acc[b][2], w1.x, d); ffma2(acc[b][3], w1.y, d);
            }
        }

        // Pipelined dot: chunk c ready -> rows 512c + {ks, ks+256}
        cp_wait<3>(); __syncthreads();
        dot_row(s_sh, w_sh, ks, b2, p0f, p1f, acc);
        dot_row(s_sh, w_sh, 256 + ks, b2, p0f, p1f, acc);
        cp_wait<2>(); __syncthreads();
        dot_row(s_sh, w_sh, 512 + ks, b2, p0f, p1f, acc);
        dot_row(s_sh, w_sh, 768 + ks, b2, p0f, p1f, acc);
        cp_wait<1>(); __syncthreads();
        dot_row(s_sh, w_sh, 1024 + ks, b2, p0f, p1f, acc);
        dot_row(s_sh, w_sh, 1280 + ks, b2, p0f, p1f, acc);
        cp_wait<0>(); __syncthreads();
        dot_row(s_sh, w_sh, 1536 + ks, b2, p0f, p1f, acc);
        dot_row(s_sh, w_sh, 1792 + ks, b2, p0f, p1f, acc);

        // Warp butterfly: 32 accs/lane -> 1 acc/lane summed over the warp's 32 ks.
        // Final lane L holds acc index bitrev5(L).
        {
            ull* A = &acc[0][0];
#pragma unroll
            for (int lev = 0; lev < 5; ++lev) {
                const int mm = 1 << lev;
                const int n = 16 >> lev;
                const bool up = (lane & mm) != 0;
#pragma unroll
                for (int q = 0; q < n; ++q) {
                    ull send = up ? A[q] : A[q + n];
                    ull recv = bfly2(send, mm);
                    ull keep = up ? A[q + n] : A[q];
                    A[q] = padd2(keep, recv);
                }
            }
            red[warp * 32 + lane] = A[0];
        }
        __syncthreads();

        // Final reduce over 8 warps per column-half + epilogue (64 threads)
        if (tid < 64) {
            const int jh2 = tid >> 5;
            const int ln = tid & 31;
            ull v = red[(jh2 * 8) * 32 + ln];
#pragma unroll
            for (int w = 1; w < 8; ++w) v = padd2(v, red[(jh2 * 8 + w) * 32 + ln]);
            // bit-reversed mapping from butterfly
            const int a = ((ln & 1) << 4) | ((ln & 2) << 2) | (ln & 4) |
                          ((ln & 8) >> 2) | ((ln & 16) >> 4);
            const int b = a >> 2;
            const int jl = jh2 * 8 + 2 * (a & 3);
            const int c0 = col0 + jl;
            float pre0 = __uint_as_float((unsigned)v) + bi_sh[jl];
            float pre1 = __uint_as_float((unsigned)(v >> 32)) + bi_sh[jl + 1];
            // old state from swizzled SMEM
            float so0 = s_sh[c0 * 8 + ((((b >> 2) ^ ((c0 >> 2) & 1))) << 2) + (b & 3)];
            float so1 = s_sh[(c0 + 1) * 8 + ((((b >> 2) ^ (((c0 + 1) >> 2) & 1))) << 2) + (b & 3)];
            float n0 = 0.5f * so0 + 0.5f * tanhf(pre0);
            float n1 = 0.5f * so1 + 0.5f * tanhf(pre1);
            float* sn = g_state[(t & 1) ^ 1];      // linear layout in global
            __stcg(sn + c0 * 8 + b, n0);
            __stcg(sn + (c0 + 1) * 8 + b, n1);
            float2 ov;                              // PowerIndex: even col squared
            ov.x = n0 * n0;
            ov.y = n1;
            *(float2*)(out + ((size_t)(b * TT + t)) * OUTF + DD + c0) = ov;
        }
        __syncthreads();

        // Arrive: release covers this CTA's epilogue stores (post-bar cumulativity)
        if (tid == 0) {
            asm volatile("red.release.gpu.global.add.u32 [%0], %1;"
                         :: "l"(&g_step_count), "r"(1u) : "memory");
        }
    }
}

__global__ void copy_inputs_kernel(const float4* __restrict__ in, float* __restrict__ out) {
    int idx = blockIdx.x * blockDim.x + threadIdx.x;
    if (idx < BB * TT * DD / 4) {
        int bt = idx >> 5;  // 32 float4 per (b,t) row
        int q = idx & 31;
        float4 v = in[idx];
        *(float4*)(out + (size_t)bt * OUTF + q * 4) = v;
    }
}

extern "C" void kernel_launch(void* const* d_in, const int* in_sizes, int n_in,
                              void* d_out, int out_size) {
    const float* inputs = (const float*)d_in[0];
    const float* w_in   = (const float*)d_in[1];
    const float* b_in   = (const float*)d_in[2];
    const float* w_res  = (const float*)d_in[3];
    float* out = (float*)d_out;

    cudaFuncSetAttribute(esn_kernel, cudaFuncAttributeMaxDynamicSharedMemorySize, SMEM_BYTES);

    copy_inputs_kernel<<<(BB * TT * DD / 4 + 255) / 256, 256>>>((const float4*)inputs, out);
    esn_kernel<<<NCTA, NTHR, SMEM_BYTES>>>(inputs, w_in, b_in, w_res, out);
}